// round 15
// baseline (speedup 1.0000x reference)
#include <cuda_runtime.h>
#include <cstdint>
#include <math.h>

#define NPIX 4096
#define NB 8
#define NC 256
#define NA 36864   // 4096*9 anchors per batch

// ---------------- device scratch (static, allocation-free) ----------------
__device__ __align__(16) float g_xin[NB*NPIX*NC];     // NHWC input
__device__ __align__(16) float g_act[NB*NPIX*NC];     // NHWC conv1 output (relu)
__device__ __align__(16) float g_wt[9*NC*NC];         // [tap][ci][co]
__device__ __align__(16) float g_ws2[NC*54];          // [ci][o]  o: 9 l0, 9 l1, 36 reg
__device__ float g_bs[54];
__device__ __align__(16) float g_props[NB*NA*4];      // decoded+clipped boxes
__device__ unsigned long long g_keys[NB*NA];          // (ord(p)<<32)|(~n)
__device__ unsigned g_hist[NB*65536];
__device__ int g_candcnt[NB];
__device__ int g_thr[NB];
__device__ unsigned long long g_cand[NB*2048];
__device__ __align__(16) float g_top[NB*1000*4];      // top-1000 sorted boxes
__device__ unsigned g_mask[NB*1000*32];               // NMS suppression bitmask

// Correctly-rounded float exp via double-precision exp.
__device__ __forceinline__ float exp_cr(float x) {
    return (float)exp((double)x);
}

// ---- packed fp32x2 helpers (each lane is an independent IEEE fp32 FMA) ----
__device__ __forceinline__ unsigned long long pack2(float x) {
    unsigned long long r;
    unsigned u = __float_as_uint(x);
    asm("mov.b64 %0, {%1, %1};" : "=l"(r) : "r"(u));
    return r;
}
__device__ __forceinline__ void unpack2(float& lo, float& hi, unsigned long long v) {
    unsigned a, b;
    asm("mov.b64 {%0, %1}, %2;" : "=r"(a), "=r"(b) : "l"(v));
    lo = __uint_as_float(a); hi = __uint_as_float(b);
}
__device__ __forceinline__ void ffma2(unsigned long long& d, unsigned long long a, unsigned long long b) {
    asm("fma.rn.f32x2 %0, %1, %2, %0;" : "+l"(d) : "l"(a), "l"(b));
}

// ---------------- init ----------------
__global__ void k_init(float* __restrict__ out) {
    int i = blockIdx.x * 256 + threadIdx.x;
    if (i < NB * 65536) g_hist[i] = 0u;
    if (i < NB) g_candcnt[i] = 0;
    if (i < NB * 300 * 5) out[i] = ((i % 5) == 0) ? (float)(i / 1500) : 0.0f;
}

// ---------------- weight prep: w_conv (co,ci,kh,kw) -> [tap][ci][co] ----------------
__global__ void k_prep_wt(const float* __restrict__ w_conv) {
    int o = blockIdx.x * 256 + threadIdx.x;     // o = (tap*256+ci)*256+co
    int co = o & 255; int rest = o >> 8; int ci = rest & 255; int tap = rest >> 8;
    g_wt[o] = w_conv[co * 2304 + ci * 9 + tap];
}

__global__ void k_prep_heads(const float* __restrict__ wclf, const float* __restrict__ bclf,
                             const float* __restrict__ wreg, const float* __restrict__ breg) {
    int o = blockIdx.x; int c = threadIdx.x;   // o in [0,54), c = ci
    float v = (o < 18) ? wclf[o * 256 + c] : wreg[(o - 18) * 256 + c];
    g_ws2[c * 54 + o] = v;
    if (c == 0) g_bs[o] = (o < 18) ? bclf[o] : breg[o - 18];
}

// ---------------- NCHW -> NHWC transpose ----------------
__global__ void k_tr(const float* __restrict__ in) {
    __shared__ float t[32][33];
    int x0 = blockIdx.x * 32;
    int y  = blockIdx.y;
    int b  = blockIdx.z >> 3;
    int cc = (blockIdx.z & 7) * 32;
    int tx = threadIdx.x, ty = threadIdx.y;
    #pragma unroll
    for (int i = 0; i < 4; i++) {
        int cl = ty + 8 * i;
        t[cl][tx] = in[((b * 256 + cc + cl) * 64 + y) * 64 + x0 + tx];
    }
    __syncthreads();
    #pragma unroll
    for (int i = 0; i < 4; i++) {
        int xl = ty + 8 * i;
        g_xin[((b * 64 + y) * 64 + x0 + xl) * 256 + cc + tx] = t[tx][xl];
    }
}

// ---------------- 3x3 conv 256->256 + bias + relu, SPLIT-K=2, pixel-pair FFMA2 ----------------
// R11 control structure (72 chunks x 32k, two syncs, explicit if/else on named
// accumulators) + R12 operand layout (A packed as native LDS.64 pixel pairs,
// B pre-duplicated {w,w} in smem). Per-output fp32 FMA chains bit-identical.
__global__ __launch_bounds__(256, 2) void k_conv(const float* __restrict__ bias) {
    constexpr int SA = 130;                          // even: keeps pixel pairs 8B-aligned
    __shared__ __align__(16) float As[32 * SA];      // [k][pixel]
    __shared__ __align__(16) float2 Bs2[32 * 64];    // [k][co] duplicated {w,w}
    int tid = threadIdx.x;
    int mb = blockIdx.x & 255;
    int nb = blockIdx.x >> 8;        // 0..3
    int pixBase = mb * 128;
    int bimg = pixBase >> 12;
    int y0 = (pixBase & 4095) >> 6;
    int cobase = nb * 64;
    int tx = tid & 15, ty = tid >> 4;       // 16 co-groups x 16 px-groups
    int lp = tid >> 3;             // 0..31 pixel row for As loads
    int lc = (tid & 7) << 2;       // k col (x4) for As loads
    int bk = tid >> 4;             // 0..15 k row for Bs loads
    int bc = (tid & 15) << 2;      // co col (x4) for Bs loads

    unsigned long long accA[4][4], accB[4][4];   // [pixel-pair][co]
    #pragma unroll
    for (int i = 0; i < 4; i++)
        #pragma unroll
        for (int j = 0; j < 4; j++) { accA[i][j] = 0ull; accB[i][j] = 0ull; }

    const float* xb = g_xin + (size_t)bimg * (NPIX * NC);

    for (int ch = 0; ch < 72; ++ch) {
        int tap = ch >> 3;
        int kc0 = (ch & 7) << 5;
        int dy = tap / 3 - 1;
        int dx = (tap % 3) - 1;

        float4 ra[4];
        #pragma unroll
        for (int v = 0; v < 4; v++) {
            int r = lp + (v << 5);
            int yy = y0 + (r >> 6) + dy;
            int xx = (r & 63) + dx;
            float4 val = make_float4(0.f, 0.f, 0.f, 0.f);
            if ((unsigned)yy < 64u && (unsigned)xx < 64u)
                val = *(const float4*)(xb + ((yy << 6) + xx) * NC + kc0 + lc);
            ra[v] = val;
        }
        float4 rb[2];
        #pragma unroll
        for (int v = 0; v < 2; v++) {
            int k = bk + (v << 4);
            rb[v] = *(const float4*)(g_wt + ((tap * NC + kc0 + k) * NC) + cobase + bc);
        }
        __syncthreads();
        #pragma unroll
        for (int v = 0; v < 4; v++) {
            int r = lp + (v << 5);
            As[(lc + 0) * SA + r] = ra[v].x;
            As[(lc + 1) * SA + r] = ra[v].y;
            As[(lc + 2) * SA + r] = ra[v].z;
            As[(lc + 3) * SA + r] = ra[v].w;
            if (v < 2) {
                int k = bk + (v << 4);
                float4* d = (float4*)&Bs2[k * 64 + bc];
                d[0] = make_float4(rb[v].x, rb[v].x, rb[v].y, rb[v].y);
                d[1] = make_float4(rb[v].z, rb[v].z, rb[v].w, rb[v].w);
            }
        }
        __syncthreads();
        if (ch < 36) {      // k in [0, 1152): partial A
            #pragma unroll 8
            for (int kk = 0; kk < 32; kk++) {
                const unsigned long long* ap =
                    (const unsigned long long*)&As[kk * SA + ty * 8];
                unsigned long long a0 = ap[0], a1 = ap[1], a2 = ap[2], a3 = ap[3];
                ulonglong2 b01 = *(const ulonglong2*)&Bs2[kk * 64 + tx * 4];
                ulonglong2 b23 = *(const ulonglong2*)&Bs2[kk * 64 + tx * 4 + 2];
                ffma2(accA[0][0], a0, b01.x); ffma2(accA[0][1], a0, b01.y);
                ffma2(accA[0][2], a0, b23.x); ffma2(accA[0][3], a0, b23.y);
                ffma2(accA[1][0], a1, b01.x); ffma2(accA[1][1], a1, b01.y);
                ffma2(accA[1][2], a1, b23.x); ffma2(accA[1][3], a1, b23.y);
                ffma2(accA[2][0], a2, b01.x); ffma2(accA[2][1], a2, b01.y);
                ffma2(accA[2][2], a2, b23.x); ffma2(accA[2][3], a2, b23.y);
                ffma2(accA[3][0], a3, b01.x); ffma2(accA[3][1], a3, b01.y);
                ffma2(accA[3][2], a3, b23.x); ffma2(accA[3][3], a3, b23.y);
            }
        } else {            // k in [1152, 2304): partial B
            #pragma unroll 8
            for (int kk = 0; kk < 32; kk++) {
                const unsigned long long* ap =
                    (const unsigned long long*)&As[kk * SA + ty * 8];
                unsigned long long a0 = ap[0], a1 = ap[1], a2 = ap[2], a3 = ap[3];
                ulonglong2 b01 = *(const ulonglong2*)&Bs2[kk * 64 + tx * 4];
                ulonglong2 b23 = *(const ulonglong2*)&Bs2[kk * 64 + tx * 4 + 2];
                ffma2(accB[0][0], a0, b01.x); ffma2(accB[0][1], a0, b01.y);
                ffma2(accB[0][2], a0, b23.x); ffma2(accB[0][3], a0, b23.y);
                ffma2(accB[1][0], a1, b01.x); ffma2(accB[1][1], a1, b01.y);
                ffma2(accB[1][2], a1, b23.x); ffma2(accB[1][3], a1, b23.y);
                ffma2(accB[2][0], a2, b01.x); ffma2(accB[2][1], a2, b01.y);
                ffma2(accB[2][2], a2, b23.x); ffma2(accB[2][3], a2, b23.y);
                ffma2(accB[3][0], a3, b01.x); ffma2(accB[3][1], a3, b01.y);
                ffma2(accB[3][2], a3, b23.x); ffma2(accB[3][3], a3, b23.y);
            }
        }
        __syncthreads();
    }
    // epilogue: (A + B) + bias, relu, NHWC store (two pixel rows per pair)
    float bq[4];
    #pragma unroll
    for (int j = 0; j < 4; j++) bq[j] = bias[cobase + tx * 4 + j];
    #pragma unroll
    for (int p = 0; p < 4; p++) {
        float alo[4], ahi[4], blo[4], bhi[4];
        #pragma unroll
        for (int j = 0; j < 4; j++) {
            unpack2(alo[j], ahi[j], accA[p][j]);
            unpack2(blo[j], bhi[j], accB[p][j]);
        }
        int gp = pixBase + ty * 8 + 2 * p;
        float* o = g_act + (size_t)gp * NC + cobase + tx * 4;
        float4 ov;
        ov.x = fmaxf(__fadd_rn(__fadd_rn(alo[0], blo[0]), bq[0]), 0.f);
        ov.y = fmaxf(__fadd_rn(__fadd_rn(alo[1], blo[1]), bq[1]), 0.f);
        ov.z = fmaxf(__fadd_rn(__fadd_rn(alo[2], blo[2]), bq[2]), 0.f);
        ov.w = fmaxf(__fadd_rn(__fadd_rn(alo[3], blo[3]), bq[3]), 0.f);
        *(float4*)o = ov;
        float* o2 = o + NC;
        float4 ov2;
        ov2.x = fmaxf(__fadd_rn(__fadd_rn(ahi[0], bhi[0]), bq[0]), 0.f);
        ov2.y = fmaxf(__fadd_rn(__fadd_rn(ahi[1], bhi[1]), bq[1]), 0.f);
        ov2.z = fmaxf(__fadd_rn(__fadd_rn(ahi[2], bhi[2]), bq[2]), 0.f);
        ov2.w = fmaxf(__fadd_rn(__fadd_rn(ahi[3], bhi[3]), bq[3]), 0.f);
        *(float4*)o2 = ov2;
    }
}

// ---------------- heads: SPLIT-K=2 over ci, packed FFMA2 pairs of outputs ----------------
__global__ __launch_bounds__(128) void k_heads(const float* __restrict__ anchors) {
    __shared__ __align__(16) float sx[128 * 33];
    __shared__ __align__(16) float sw[32 * 54];
    int tid = threadIdx.x;
    int p0 = blockIdx.x * 128;
    unsigned long long accA2[27], accB2[27];    // packed (o, o+1) output pairs
    #pragma unroll
    for (int o = 0; o < 27; o++) { accA2[o] = 0ull; accB2[o] = 0ull; }

    for (int cc = 0; cc < 8; cc++) {
        __syncthreads();
        for (int i = tid; i < 1024; i += 128) {
            int px = i >> 3, cg = (i & 7) << 2;
            float4 v = *(const float4*)&g_act[(size_t)(p0 + px) * 256 + cc * 32 + cg];
            sx[px * 33 + cg + 0] = v.x;
            sx[px * 33 + cg + 1] = v.y;
            sx[px * 33 + cg + 2] = v.z;
            sx[px * 33 + cg + 3] = v.w;
        }
        for (int i = tid; i < 1728; i += 128) sw[i] = g_ws2[cc * 32 * 54 + i];
        __syncthreads();
        if (cc < 4) {       // ci in [0,128): partial A
            for (int cl = 0; cl < 32; cl++) {
                unsigned long long x2 = pack2(sx[tid * 33 + cl]);
                #pragma unroll
                for (int o2 = 0; o2 < 27; o2++)
                    ffma2(accA2[o2], x2, *(const unsigned long long*)&sw[cl * 54 + 2 * o2]);
            }
        } else {            // ci in [128,256): partial B
            for (int cl = 0; cl < 32; cl++) {
                unsigned long long x2 = pack2(sx[tid * 33 + cl]);
                #pragma unroll
                for (int o2 = 0; o2 < 27; o2++)
                    ffma2(accB2[o2], x2, *(const unsigned long long*)&sw[cl * 54 + 2 * o2]);
            }
        }
    }
    float acc[54];
    #pragma unroll
    for (int o2 = 0; o2 < 27; o2++) {
        float la, ha, lb, hb;
        unpack2(la, ha, accA2[o2]);
        unpack2(lb, hb, accB2[o2]);
        acc[2 * o2 + 0] = __fadd_rn(__fadd_rn(la, lb), g_bs[2 * o2 + 0]);
        acc[2 * o2 + 1] = __fadd_rn(__fadd_rn(ha, hb), g_bs[2 * o2 + 1]);
    }

    int p = p0 + tid;           // global pixel 0..32767
    int b = p >> 12;
    #pragma unroll
    for (int a = 0; a < 9; a++) {
        float l0 = acc[a];
        float l1 = acc[9 + a];
        float r0 = acc[18 + 4 * a + 0];
        float r1 = acc[18 + 4 * a + 1];
        float r2 = acc[18 + 4 * a + 2];
        float r3 = acc[18 + 4 * a + 3];
        // softmax prob of class 1: fp32 op-by-op (jax.nn.softmax structure)
        float m  = fmaxf(l0, l1);
        float e0 = exp_cr(__fsub_rn(l0, m));
        float e1 = exp_cr(__fsub_rn(l1, m));
        float pr = __fdiv_rn(e1, __fadd_rn(e0, e1));
        int n = (p & 4095) * 9 + a;
        float4 an = ((const float4*)anchors)[n];
        float szx = __fsub_rn(an.z, an.x), szy = __fsub_rn(an.w, an.y);
        float cx = __fmul_rn(0.5f, __fadd_rn(an.x, an.z));
        float cy = __fmul_rn(0.5f, __fadd_rn(an.y, an.w));
        float pcx = __fadd_rn(__fmul_rn(r0, szx), cx);
        float pcy = __fadd_rn(__fmul_rn(r1, szy), cy);
        float psx = __fmul_rn(exp_cr(r2), szx);
        float psy = __fmul_rn(exp_cr(r3), szy);
        float x1 = __fsub_rn(pcx, __fmul_rn(0.5f, psx));
        float y1 = __fsub_rn(pcy, __fmul_rn(0.5f, psy));
        float x2 = __fadd_rn(pcx, __fmul_rn(0.5f, psx));
        float y2 = __fadd_rn(pcy, __fmul_rn(0.5f, psy));
        x1 = fminf(fmaxf(x1, 0.f), 1023.f);
        y1 = fminf(fmaxf(y1, 0.f), 1023.f);
        x2 = fminf(fmaxf(x2, 0.f), 1023.f);
        y2 = fminf(fmaxf(y2, 0.f), 1023.f);
        ((float4*)g_props)[b * NA + n] = make_float4(x1, y1, x2, y2);
        unsigned u = __float_as_uint(pr) | 0x80000000u;   // pr > 0 always
        g_keys[b * NA + n] = ((unsigned long long)u << 32)
                           | (unsigned long long)(0xFFFFFFFFu - (unsigned)n);
        atomicAdd(&g_hist[(b << 16) + (u >> 16)], 1u);
    }
}

// ---------------- radix-select threshold bin for top-1000 ----------------
__global__ void k_select() {
    int b = blockIdx.x;
    __shared__ unsigned csum[256];
    const unsigned* h = g_hist + b * 65536;
    unsigned s = 0;
    int base = threadIdx.x * 256;
    for (int i = 0; i < 256; i++) s += h[base + i];
    csum[threadIdx.x] = s;
    __syncthreads();
    if (threadIdx.x == 0) {
        unsigned acc = 0;
        int t = 255;
        for (; t >= 0; --t) {
            if (acc + csum[t] >= 1000u) break;
            acc += csum[t];
        }
        int T = 0;
        for (int i = 255; i >= 0; --i) {
            unsigned c = h[t * 256 + i];
            if (acc + c >= 1000u) { T = t * 256 + i; break; }
            acc += c;
        }
        g_thr[b] = T;
    }
}

__global__ void k_collect() {
    int b = blockIdx.y;
    int i = blockIdx.x * 256 + threadIdx.x;
    if (i >= NA) return;
    unsigned long long key = g_keys[b * NA + i];
    unsigned bin = (unsigned)(key >> 48);
    if (bin >= (unsigned)g_thr[b]) {
        int pos = atomicAdd(&g_candcnt[b], 1);
        if (pos < 2048) g_cand[b * 2048 + pos] = key;
    }
}

// ---------------- bitonic sort candidates (desc), gather top-1000 ----------------
__global__ __launch_bounds__(1024) void k_sort() {
    __shared__ unsigned long long sk[2048];
    int b = blockIdx.x;
    int tid = threadIdx.x;
    int cnt = g_candcnt[b];
    if (cnt > 2048) cnt = 2048;
    sk[tid]        = (tid < cnt)        ? g_cand[b * 2048 + tid]        : 0ULL;
    sk[tid + 1024] = (tid + 1024 < cnt) ? g_cand[b * 2048 + tid + 1024] : 0ULL;
    for (int k = 2; k <= 2048; k <<= 1) {
        for (int j = k >> 1; j > 0; j >>= 1) {
            __syncthreads();
            int i = ((tid & ~(j - 1)) << 1) | (tid & (j - 1));
            int l = i | j;
            bool desc = ((i & k) == 0);
            unsigned long long a = sk[i], cc = sk[l];
            if ((a < cc) == desc) { sk[i] = cc; sk[l] = a; }
        }
    }
    __syncthreads();
    if (tid < 1000) {
        unsigned long long key = sk[tid];
        unsigned n = 0xFFFFFFFFu - (unsigned)key;
        float4 pr = ((const float4*)g_props)[b * NA + n];
        ((float4*)g_top)[b * 1000 + tid] = pr;
    }
}

// ---------------- NMS suppression bitmask (fp32 IEEE) ----------------
__global__ void k_mask() {
    __shared__ float4 sbx[1000];
    int b = blockIdx.y;
    int i = blockIdx.x * 128 + threadIdx.x;
    for (int j = threadIdx.x; j < 1000; j += 128)
        sbx[j] = ((const float4*)g_top)[b * 1000 + j];
    __syncthreads();
    if (i >= 1000) return;
    float4 bi = sbx[i];
    float ai = __fmul_rn(__fsub_rn(bi.z, bi.x), __fsub_rn(bi.w, bi.y));
    unsigned word = 0;
    for (int j = 0; j < 1024; j++) {
        if (j < 1000) {
            float4 bj = sbx[j];
            float lbx = fmaxf(bi.x, bj.x), lby = fmaxf(bi.y, bj.y);
            float ubx = fminf(bi.z, bj.z), uby = fminf(bi.w, bj.w);
            float inter = __fmul_rn(fmaxf(__fsub_rn(ubx, lbx), 0.f),
                                    fmaxf(__fsub_rn(uby, lby), 0.f));
            float aj = __fmul_rn(__fsub_rn(bj.z, bj.x), __fsub_rn(bj.w, bj.y));
            float uni = __fsub_rn(__fadd_rn(ai, aj), inter);
            float iou = __fdiv_rn(inter, uni);
            if ((j > i) && (iou > 0.7f)) word |= 1u << (j & 31);
        }
        if ((j & 31) == 31) {
            g_mask[(b * 1000 + i) * 32 + (j >> 5)] = word;
            word = 0;
        }
    }
}

// ---------------- sequential NMS scan + compaction ----------------
__global__ void k_scan(float* __restrict__ out) {
    int b = blockIdx.x;
    int lane = threadIdx.x;
    unsigned keep = (lane < 31) ? 0xFFFFFFFFu : 0x000000FFu;  // bits 0..999
    const unsigned* mrow = g_mask + (size_t)b * 1000 * 32;
    for (int i = 0; i < 1000; i++) {
        unsigned kw = __shfl_sync(0xffffffffu, keep, i >> 5);
        if ((kw >> (i & 31)) & 1u)
            keep &= ~mrow[i * 32 + lane];
    }
    int cnt = __popc(keep);
    int pre = cnt;
    #pragma unroll
    for (int off = 1; off < 32; off <<= 1) {
        int nn = __shfl_up_sync(0xffffffffu, pre, off);
        if (lane >= off) pre += nn;
    }
    int r = pre - cnt;  // exclusive prefix
    unsigned m = keep;
    while (m) {
        int bit = __ffs(m) - 1;
        m &= m - 1;
        if (r < 300) {
            int idx = lane * 32 + bit;
            float4 bx = ((const float4*)g_top)[b * 1000 + idx];
            float* o = out + (b * 300 + r) * 5;
            o[0] = (float)b;
            o[1] = bx.x; o[2] = bx.y; o[3] = bx.z; o[4] = bx.w;
        }
        r++;
    }
}

// ---------------- launch ----------------
extern "C" void kernel_launch(void* const* d_in, const int* in_sizes, int n_in,
                              void* d_out, int out_size) {
    const float *inputs = nullptr, *anchors = nullptr, *w_conv = nullptr, *b_conv = nullptr;
    const float *w_clf = nullptr, *b_clf = nullptr, *w_reg = nullptr, *b_reg = nullptr;
    for (int i = 0; i < n_in; i++) {
        switch (in_sizes[i]) {
            case 8388608: inputs  = (const float*)d_in[i]; break;
            case 147456:  anchors = (const float*)d_in[i]; break;
            case 589824:  w_conv  = (const float*)d_in[i]; break;
            case 256:     b_conv  = (const float*)d_in[i]; break;
            case 4608:    w_clf   = (const float*)d_in[i]; break;
            case 18:      b_clf   = (const float*)d_in[i]; break;
            case 9216:    w_reg   = (const float*)d_in[i]; break;
            case 36:      b_reg   = (const float*)d_in[i]; break;
            default: break; // bboxes (512) unused
        }
    }
    float* out = (float*)d_out;

    k_init<<<2048, 256>>>(out);
    k_prep_wt<<<2304, 256>>>(w_conv);
    k_prep_heads<<<54, 256>>>(w_clf, b_clf, w_reg, b_reg);
    k_tr<<<dim3(2, 64, 64), dim3(32, 8)>>>(inputs);
    k_conv<<<1024, 256>>>(b_conv);
    k_heads<<<256, 128>>>(anchors);
    k_select<<<8, 256>>>();
    k_collect<<<dim3(144, 8), 256>>>();
    k_sort<<<8, 1024>>>();
    k_mask<<<dim3(8, 8), 128>>>();
    k_scan<<<8, 32>>>(out);
    (void)out_size;
}

// round 16
// speedup vs baseline: 1.4748x; 1.4748x over previous
#include <cuda_runtime.h>
#include <cstdint>
#include <math.h>

#define NPIX 4096
#define NB 8
#define NC 256
#define NA 36864   // 4096*9 anchors per batch

// ---------------- device scratch (static, allocation-free) ----------------
__device__ __align__(16) float g_xin[NB*NPIX*NC];     // NHWC input
__device__ __align__(16) float g_act[NB*NPIX*NC];     // NHWC conv1 output (relu)
__device__ __align__(16) float g_wt[9*NC*NC];         // [tap][ci][co]
__device__ __align__(16) float g_ws2[NC*54];          // [ci][o]  o: 9 l0, 9 l1, 36 reg
__device__ float g_bs[54];
__device__ __align__(16) float g_props[NB*NA*4];      // decoded+clipped boxes
__device__ unsigned long long g_keys[NB*NA];          // (ord(p)<<32)|(~n)
__device__ unsigned g_hist[NB*65536];
__device__ int g_candcnt[NB];
__device__ int g_thr[NB];
__device__ unsigned long long g_cand[NB*2048];
__device__ __align__(16) float g_top[NB*1000*4];      // top-1000 sorted boxes
__device__ unsigned g_mask[NB*1000*32];               // NMS suppression bitmask

// Correctly-rounded float exp via double-precision exp.
__device__ __forceinline__ float exp_cr(float x) {
    return (float)exp((double)x);
}

// ---- packed fp32x2 helpers (each lane is an independent IEEE fp32 FMA) ----
__device__ __forceinline__ unsigned long long pack2(float x) {
    unsigned long long r;
    unsigned u = __float_as_uint(x);
    asm("mov.b64 %0, {%1, %1};" : "=l"(r) : "r"(u));
    return r;
}
__device__ __forceinline__ void unpack2(float& lo, float& hi, unsigned long long v) {
    unsigned a, b;
    asm("mov.b64 {%0, %1}, %2;" : "=r"(a), "=r"(b) : "l"(v));
    lo = __uint_as_float(a); hi = __uint_as_float(b);
}
__device__ __forceinline__ void ffma2(unsigned long long& d, unsigned long long a, unsigned long long b) {
    asm("fma.rn.f32x2 %0, %1, %2, %0;" : "+l"(d) : "l"(a), "l"(b));
}

// ---------------- init ----------------
__global__ void k_init(float* __restrict__ out) {
    int i = blockIdx.x * 256 + threadIdx.x;
    if (i < NB * 65536) g_hist[i] = 0u;
    if (i < NB) g_candcnt[i] = 0;
    if (i < NB * 300 * 5) out[i] = ((i % 5) == 0) ? (float)(i / 1500) : 0.0f;
}

// ---------------- weight prep: w_conv (co,ci,kh,kw) -> [tap][ci][co] ----------------
__global__ void k_prep_wt(const float* __restrict__ w_conv) {
    int o = blockIdx.x * 256 + threadIdx.x;     // o = (tap*256+ci)*256+co
    int co = o & 255; int rest = o >> 8; int ci = rest & 255; int tap = rest >> 8;
    g_wt[o] = w_conv[co * 2304 + ci * 9 + tap];
}

__global__ void k_prep_heads(const float* __restrict__ wclf, const float* __restrict__ bclf,
                             const float* __restrict__ wreg, const float* __restrict__ breg) {
    int o = blockIdx.x; int c = threadIdx.x;   // o in [0,54), c = ci
    float v = (o < 18) ? wclf[o * 256 + c] : wreg[(o - 18) * 256 + c];
    g_ws2[c * 54 + o] = v;
    if (c == 0) g_bs[o] = (o < 18) ? bclf[o] : breg[o - 18];
}

// ---------------- NCHW -> NHWC transpose ----------------
__global__ void k_tr(const float* __restrict__ in) {
    __shared__ float t[32][33];
    int x0 = blockIdx.x * 32;
    int y  = blockIdx.y;
    int b  = blockIdx.z >> 3;
    int cc = (blockIdx.z & 7) * 32;
    int tx = threadIdx.x, ty = threadIdx.y;
    #pragma unroll
    for (int i = 0; i < 4; i++) {
        int cl = ty + 8 * i;
        t[cl][tx] = in[((b * 256 + cc + cl) * 64 + y) * 64 + x0 + tx];
    }
    __syncthreads();
    #pragma unroll
    for (int i = 0; i < 4; i++) {
        int xl = ty + 8 * i;
        g_xin[((b * 64 + y) * 64 + x0 + xl) * 256 + cc + tx] = t[tx][xl];
    }
}

// ---------------- 3x3 conv 256->256 + bias + relu, SPLIT-K=2, FFMA2, pipelined ----------------
// R11's exact staging + inner loop (32-k chunks, co-pair FFMA2 packing), now
// double-buffered in dynamic smem: one sync per chunk, LDG latency hidden behind
// the previous chunk's compute. Per-output fp32 FMA chains bit-identical to R11.
__global__ __launch_bounds__(256, 2) void k_conv(const float* __restrict__ bias) {
    constexpr int SA = 129;
    constexpr int ASZ = 32 * SA;    // 4128 floats per buffer
    constexpr int BSZ = 32 * 64;    // 2048 floats per buffer
    extern __shared__ float sm[];
    float* Asm = sm;                // [2][ASZ]
    float* Bsm = sm + 2 * ASZ;      // [2][BSZ]
    int tid = threadIdx.x;
    int mb = blockIdx.x & 255;
    int nb = blockIdx.x >> 8;        // 0..3
    int pixBase = mb * 128;
    int bimg = pixBase >> 12;
    int y0 = (pixBase & 4095) >> 6;
    int cobase = nb * 64;
    int tx = tid & 15, ty = tid >> 4;       // 16 co-groups x 16 px-groups
    int lp = tid >> 3;             // 0..31 pixel row for As loads
    int lc = (tid & 7) << 2;       // k col (x4) for As loads
    int bk = tid >> 4;             // 0..15 k row for Bs loads
    int bc = (tid & 15) << 2;      // co col (x4) for Bs loads

    unsigned long long accA[8][2], accB[8][2];   // [pixel][co-pair]
    #pragma unroll
    for (int i = 0; i < 8; i++) {
        accA[i][0] = 0ull; accA[i][1] = 0ull;
        accB[i][0] = 0ull; accB[i][1] = 0ull;
    }

    const float* xb = g_xin + (size_t)bimg * (NPIX * NC);

    auto load_chunk = [&](int ch, float4 (&ra)[4], float4 (&rb)[2]) {
        int tap = ch >> 3;
        int kc0 = (ch & 7) << 5;
        int dy = tap / 3 - 1;
        int dx = (tap % 3) - 1;
        #pragma unroll
        for (int v = 0; v < 4; v++) {
            int r = lp + (v << 5);
            int yy = y0 + (r >> 6) + dy;
            int xx = (r & 63) + dx;
            float4 val = make_float4(0.f, 0.f, 0.f, 0.f);
            if ((unsigned)yy < 64u && (unsigned)xx < 64u)
                val = *(const float4*)(xb + ((yy << 6) + xx) * NC + kc0 + lc);
            ra[v] = val;
        }
        #pragma unroll
        for (int v = 0; v < 2; v++) {
            int k = bk + (v << 4);
            rb[v] = *(const float4*)(g_wt + ((tap * NC + kc0 + k) * NC) + cobase + bc);
        }
    };
    auto store_chunk = [&](int buf, const float4 (&ra)[4], const float4 (&rb)[2]) {
        float* As = Asm + buf * ASZ;
        float* Bs = Bsm + buf * BSZ;
        #pragma unroll
        for (int v = 0; v < 4; v++) {
            int r = lp + (v << 5);
            As[(lc + 0) * SA + r] = ra[v].x;
            As[(lc + 1) * SA + r] = ra[v].y;
            As[(lc + 2) * SA + r] = ra[v].z;
            As[(lc + 3) * SA + r] = ra[v].w;
            if (v < 2) {
                int k = bk + (v << 4);
                *(float4*)&Bs[k * 64 + bc] = rb[v];
            }
        }
    };

    float4 ra[4], rb[2];
    load_chunk(0, ra, rb);
    store_chunk(0, ra, rb);
    for (int ch = 0; ch < 72; ++ch) {
        float4 ran[4], rbn[2];
        if (ch < 71) load_chunk(ch + 1, ran, rbn);
        __syncthreads();      // chunk ch fully staged; all warps done with other buffer
        const float* As = Asm + (ch & 1) * ASZ;
        const float* Bs = Bsm + (ch & 1) * BSZ;
        if (ch < 36) {      // k in [0, 1152): partial A
            #pragma unroll 8
            for (int kk = 0; kk < 32; kk++) {
                unsigned long long a2[8];
                #pragma unroll
                for (int i = 0; i < 8; i++) a2[i] = pack2(As[kk * SA + ty * 8 + i]);
                ulonglong2 bb = *(const ulonglong2*)&Bs[kk * 64 + tx * 4];
                #pragma unroll
                for (int i = 0; i < 8; i++) {
                    ffma2(accA[i][0], a2[i], bb.x);
                    ffma2(accA[i][1], a2[i], bb.y);
                }
            }
        } else {            // k in [1152, 2304): partial B
            #pragma unroll 8
            for (int kk = 0; kk < 32; kk++) {
                unsigned long long a2[8];
                #pragma unroll
                for (int i = 0; i < 8; i++) a2[i] = pack2(As[kk * SA + ty * 8 + i]);
                ulonglong2 bb = *(const ulonglong2*)&Bs[kk * 64 + tx * 4];
                #pragma unroll
                for (int i = 0; i < 8; i++) {
                    ffma2(accB[i][0], a2[i], bb.x);
                    ffma2(accB[i][1], a2[i], bb.y);
                }
            }
        }
        if (ch < 71) store_chunk((ch + 1) & 1, ran, rbn);
    }

    // epilogue: (A + B) + bias, relu, NHWC store
    float bq[4];
    #pragma unroll
    for (int j = 0; j < 4; j++) bq[j] = bias[cobase + tx * 4 + j];
    #pragma unroll
    for (int i = 0; i < 8; i++) {
        int gp = pixBase + ty * 8 + i;
        float* o = g_act + (size_t)gp * NC + cobase + tx * 4;
        float a0, a1, a2v, a3, b0, b1, b2, b3;
        unpack2(a0, a1, accA[i][0]); unpack2(a2v, a3, accA[i][1]);
        unpack2(b0, b1, accB[i][0]); unpack2(b2, b3, accB[i][1]);
        float4 ov;
        ov.x = fmaxf(__fadd_rn(__fadd_rn(a0,  b0), bq[0]), 0.f);
        ov.y = fmaxf(__fadd_rn(__fadd_rn(a1,  b1), bq[1]), 0.f);
        ov.z = fmaxf(__fadd_rn(__fadd_rn(a2v, b2), bq[2]), 0.f);
        ov.w = fmaxf(__fadd_rn(__fadd_rn(a3,  b3), bq[3]), 0.f);
        *(float4*)o = ov;
    }
}

// ---------------- heads: SPLIT-K=2 over ci, packed FFMA2 pairs of outputs ----------------
__global__ __launch_bounds__(128) void k_heads(const float* __restrict__ anchors) {
    __shared__ __align__(16) float sx[128 * 33];
    __shared__ __align__(16) float sw[32 * 54];
    int tid = threadIdx.x;
    int p0 = blockIdx.x * 128;
    unsigned long long accA2[27], accB2[27];    // packed (o, o+1) output pairs
    #pragma unroll
    for (int o = 0; o < 27; o++) { accA2[o] = 0ull; accB2[o] = 0ull; }

    for (int cc = 0; cc < 8; cc++) {
        __syncthreads();
        for (int i = tid; i < 1024; i += 128) {
            int px = i >> 3, cg = (i & 7) << 2;
            float4 v = *(const float4*)&g_act[(size_t)(p0 + px) * 256 + cc * 32 + cg];
            sx[px * 33 + cg + 0] = v.x;
            sx[px * 33 + cg + 1] = v.y;
            sx[px * 33 + cg + 2] = v.z;
            sx[px * 33 + cg + 3] = v.w;
        }
        for (int i = tid; i < 1728; i += 128) sw[i] = g_ws2[cc * 32 * 54 + i];
        __syncthreads();
        if (cc < 4) {       // ci in [0,128): partial A
            for (int cl = 0; cl < 32; cl++) {
                unsigned long long x2 = pack2(sx[tid * 33 + cl]);
                #pragma unroll
                for (int o2 = 0; o2 < 27; o2++)
                    ffma2(accA2[o2], x2, *(const unsigned long long*)&sw[cl * 54 + 2 * o2]);
            }
        } else {            // ci in [128,256): partial B
            for (int cl = 0; cl < 32; cl++) {
                unsigned long long x2 = pack2(sx[tid * 33 + cl]);
                #pragma unroll
                for (int o2 = 0; o2 < 27; o2++)
                    ffma2(accB2[o2], x2, *(const unsigned long long*)&sw[cl * 54 + 2 * o2]);
            }
        }
    }
    float acc[54];
    #pragma unroll
    for (int o2 = 0; o2 < 27; o2++) {
        float la, ha, lb, hb;
        unpack2(la, ha, accA2[o2]);
        unpack2(lb, hb, accB2[o2]);
        acc[2 * o2 + 0] = __fadd_rn(__fadd_rn(la, lb), g_bs[2 * o2 + 0]);
        acc[2 * o2 + 1] = __fadd_rn(__fadd_rn(ha, hb), g_bs[2 * o2 + 1]);
    }

    int p = p0 + tid;           // global pixel 0..32767
    int b = p >> 12;
    #pragma unroll
    for (int a = 0; a < 9; a++) {
        float l0 = acc[a];
        float l1 = acc[9 + a];
        float r0 = acc[18 + 4 * a + 0];
        float r1 = acc[18 + 4 * a + 1];
        float r2 = acc[18 + 4 * a + 2];
        float r3 = acc[18 + 4 * a + 3];
        // softmax prob of class 1: fp32 op-by-op (jax.nn.softmax structure)
        float m  = fmaxf(l0, l1);
        float e0 = exp_cr(__fsub_rn(l0, m));
        float e1 = exp_cr(__fsub_rn(l1, m));
        float pr = __fdiv_rn(e1, __fadd_rn(e0, e1));
        int n = (p & 4095) * 9 + a;
        float4 an = ((const float4*)anchors)[n];
        float szx = __fsub_rn(an.z, an.x), szy = __fsub_rn(an.w, an.y);
        float cx = __fmul_rn(0.5f, __fadd_rn(an.x, an.z));
        float cy = __fmul_rn(0.5f, __fadd_rn(an.y, an.w));
        float pcx = __fadd_rn(__fmul_rn(r0, szx), cx);
        float pcy = __fadd_rn(__fmul_rn(r1, szy), cy);
        float psx = __fmul_rn(exp_cr(r2), szx);
        float psy = __fmul_rn(exp_cr(r3), szy);
        float x1 = __fsub_rn(pcx, __fmul_rn(0.5f, psx));
        float y1 = __fsub_rn(pcy, __fmul_rn(0.5f, psy));
        float x2 = __fadd_rn(pcx, __fmul_rn(0.5f, psx));
        float y2 = __fadd_rn(pcy, __fmul_rn(0.5f, psy));
        x1 = fminf(fmaxf(x1, 0.f), 1023.f);
        y1 = fminf(fmaxf(y1, 0.f), 1023.f);
        x2 = fminf(fmaxf(x2, 0.f), 1023.f);
        y2 = fminf(fmaxf(y2, 0.f), 1023.f);
        ((float4*)g_props)[b * NA + n] = make_float4(x1, y1, x2, y2);
        unsigned u = __float_as_uint(pr) | 0x80000000u;   // pr > 0 always
        g_keys[b * NA + n] = ((unsigned long long)u << 32)
                           | (unsigned long long)(0xFFFFFFFFu - (unsigned)n);
        atomicAdd(&g_hist[(b << 16) + (u >> 16)], 1u);
    }
}

// ---------------- radix-select threshold bin for top-1000 ----------------
__global__ void k_select() {
    int b = blockIdx.x;
    __shared__ unsigned csum[256];
    const unsigned* h = g_hist + b * 65536;
    unsigned s = 0;
    int base = threadIdx.x * 256;
    for (int i = 0; i < 256; i++) s += h[base + i];
    csum[threadIdx.x] = s;
    __syncthreads();
    if (threadIdx.x == 0) {
        unsigned acc = 0;
        int t = 255;
        for (; t >= 0; --t) {
            if (acc + csum[t] >= 1000u) break;
            acc += csum[t];
        }
        int T = 0;
        for (int i = 255; i >= 0; --i) {
            unsigned c = h[t * 256 + i];
            if (acc + c >= 1000u) { T = t * 256 + i; break; }
            acc += c;
        }
        g_thr[b] = T;
    }
}

__global__ void k_collect() {
    int b = blockIdx.y;
    int i = blockIdx.x * 256 + threadIdx.x;
    if (i >= NA) return;
    unsigned long long key = g_keys[b * NA + i];
    unsigned bin = (unsigned)(key >> 48);
    if (bin >= (unsigned)g_thr[b]) {
        int pos = atomicAdd(&g_candcnt[b], 1);
        if (pos < 2048) g_cand[b * 2048 + pos] = key;
    }
}

// ---------------- bitonic sort candidates (desc), gather top-1000 ----------------
__global__ __launch_bounds__(1024) void k_sort() {
    __shared__ unsigned long long sk[2048];
    int b = blockIdx.x;
    int tid = threadIdx.x;
    int cnt = g_candcnt[b];
    if (cnt > 2048) cnt = 2048;
    sk[tid]        = (tid < cnt)        ? g_cand[b * 2048 + tid]        : 0ULL;
    sk[tid + 1024] = (tid + 1024 < cnt) ? g_cand[b * 2048 + tid + 1024] : 0ULL;
    for (int k = 2; k <= 2048; k <<= 1) {
        for (int j = k >> 1; j > 0; j >>= 1) {
            __syncthreads();
            int i = ((tid & ~(j - 1)) << 1) | (tid & (j - 1));
            int l = i | j;
            bool desc = ((i & k) == 0);
            unsigned long long a = sk[i], cc = sk[l];
            if ((a < cc) == desc) { sk[i] = cc; sk[l] = a; }
        }
    }
    __syncthreads();
    if (tid < 1000) {
        unsigned long long key = sk[tid];
        unsigned n = 0xFFFFFFFFu - (unsigned)key;
        float4 pr = ((const float4*)g_props)[b * NA + n];
        ((float4*)g_top)[b * 1000 + tid] = pr;
    }
}

// ---------------- NMS suppression bitmask (fp32 IEEE) ----------------
__global__ void k_mask() {
    __shared__ float4 sbx[1000];
    int b = blockIdx.y;
    int i = blockIdx.x * 128 + threadIdx.x;
    for (int j = threadIdx.x; j < 1000; j += 128)
        sbx[j] = ((const float4*)g_top)[b * 1000 + j];
    __syncthreads();
    if (i >= 1000) return;
    float4 bi = sbx[i];
    float ai = __fmul_rn(__fsub_rn(bi.z, bi.x), __fsub_rn(bi.w, bi.y));
    unsigned word = 0;
    for (int j = 0; j < 1024; j++) {
        if (j < 1000) {
            float4 bj = sbx[j];
            float lbx = fmaxf(bi.x, bj.x), lby = fmaxf(bi.y, bj.y);
            float ubx = fminf(bi.z, bj.z), uby = fminf(bi.w, bj.w);
            float inter = __fmul_rn(fmaxf(__fsub_rn(ubx, lbx), 0.f),
                                    fmaxf(__fsub_rn(uby, lby), 0.f));
            float aj = __fmul_rn(__fsub_rn(bj.z, bj.x), __fsub_rn(bj.w, bj.y));
            float uni = __fsub_rn(__fadd_rn(ai, aj), inter);
            float iou = __fdiv_rn(inter, uni);
            if ((j > i) && (iou > 0.7f)) word |= 1u << (j & 31);
        }
        if ((j & 31) == 31) {
            g_mask[(b * 1000 + i) * 32 + (j >> 5)] = word;
            word = 0;
        }
    }
}

// ---------------- sequential NMS scan + compaction ----------------
__global__ void k_scan(float* __restrict__ out) {
    int b = blockIdx.x;
    int lane = threadIdx.x;
    unsigned keep = (lane < 31) ? 0xFFFFFFFFu : 0x000000FFu;  // bits 0..999
    const unsigned* mrow = g_mask + (size_t)b * 1000 * 32;
    for (int i = 0; i < 1000; i++) {
        unsigned kw = __shfl_sync(0xffffffffu, keep, i >> 5);
        if ((kw >> (i & 31)) & 1u)
            keep &= ~mrow[i * 32 + lane];
    }
    int cnt = __popc(keep);
    int pre = cnt;
    #pragma unroll
    for (int off = 1; off < 32; off <<= 1) {
        int nn = __shfl_up_sync(0xffffffffu, pre, off);
        if (lane >= off) pre += nn;
    }
    int r = pre - cnt;  // exclusive prefix
    unsigned m = keep;
    while (m) {
        int bit = __ffs(m) - 1;
        m &= m - 1;
        if (r < 300) {
            int idx = lane * 32 + bit;
            float4 bx = ((const float4*)g_top)[b * 1000 + idx];
            float* o = out + (b * 300 + r) * 5;
            o[0] = (float)b;
            o[1] = bx.x; o[2] = bx.y; o[3] = bx.z; o[4] = bx.w;
        }
        r++;
    }
}

// ---------------- launch ----------------
extern "C" void kernel_launch(void* const* d_in, const int* in_sizes, int n_in,
                              void* d_out, int out_size) {
    const float *inputs = nullptr, *anchors = nullptr, *w_conv = nullptr, *b_conv = nullptr;
    const float *w_clf = nullptr, *b_clf = nullptr, *w_reg = nullptr, *b_reg = nullptr;
    for (int i = 0; i < n_in; i++) {
        switch (in_sizes[i]) {
            case 8388608: inputs  = (const float*)d_in[i]; break;
            case 147456:  anchors = (const float*)d_in[i]; break;
            case 589824:  w_conv  = (const float*)d_in[i]; break;
            case 256:     b_conv  = (const float*)d_in[i]; break;
            case 4608:    w_clf   = (const float*)d_in[i]; break;
            case 18:      b_clf   = (const float*)d_in[i]; break;
            case 9216:    w_reg   = (const float*)d_in[i]; break;
            case 36:      b_reg   = (const float*)d_in[i]; break;
            default: break; // bboxes (512) unused
        }
    }
    float* out = (float*)d_out;
    constexpr int CONV_SMEM = (2 * 32 * 129 + 2 * 32 * 64) * 4;   // 49408 bytes
    static bool attr_set = false;
    if (!attr_set) {
        cudaFuncSetAttribute(k_conv, cudaFuncAttributeMaxDynamicSharedMemorySize, CONV_SMEM);
        attr_set = true;
    }

    k_init<<<2048, 256>>>(out);
    k_prep_wt<<<2304, 256>>>(w_conv);
    k_prep_heads<<<54, 256>>>(w_clf, b_clf, w_reg, b_reg);
    k_tr<<<dim3(2, 64, 64), dim3(32, 8)>>>(inputs);
    k_conv<<<1024, 256, CONV_SMEM>>>(b_conv);
    k_heads<<<256, 128>>>(anchors);
    k_select<<<8, 256>>>();
    k_collect<<<dim3(144, 8), 256>>>();
    k_sort<<<8, 1024>>>();
    k_mask<<<dim3(8, 8), 128>>>();
    k_scan<<<8, 32>>>(out);
    (void)out_size;
}